// round 14
// baseline (speedup 1.0000x reference)
#include <cuda_runtime.h>
#include <cuda_fp16.h>
#include <math.h>
#include <stdint.h>

// ---------------------------------------------------------------------------
// Problem constants
// ---------------------------------------------------------------------------
#define BATCH 32
#define CIN   256
#define COUT  256
#define HW_H  56
#define HW_W  56
#define HW    3136
#define KTAPS 9
#define M_TOT (BATCH * HW)               // 100352

#define M_TILE   96
#define N_TILE   128
#define THREADS  128                     // 4 warps (2x2), warp tile 48x64
#define KC       64                      // ci per K chunk (4 k16 steps)
#define NCHUNKS  (KTAPS * (CIN / KC))    // 36
#define M_TILES  ((M_TOT + M_TILE - 1) / M_TILE)   // 1046 (last partial)

// A halo tile: rows m0-57 .. m0+152 (210 rows) + 1 zero row, one ci-chunk.
// Row-usage fact: taps 6/7/8 (dy=+1) read only rows >=112 (plus ZROW), so
// rows [0,112) of the NEXT ci-chunk can be preloaded during tap 6.
#define A_ROWS   211
#define ZROW     210
#define A_SPLIT  112                     // rows [0,112) preloadable at tap 6
#define A_TILE_B (A_ROWS * 128)          // 27008
#define B_BYTES  (N_TILE * KC * 2)       // 16384
#define SMEM_DYN (A_TILE_B + 3 * B_BYTES) // 76160 -> 3 CTAs/SM (233,088 B total)

// ---------------------------------------------------------------------------
// Global scratch
// ---------------------------------------------------------------------------
__device__ __align__(16) __half g_a[(size_t)M_TOT * CIN];    // NHWC fp16
__device__ __align__(16) __half g_w[KTAPS * COUT * CIN];     // [tap][oc][ci]

// ---------------------------------------------------------------------------
// PTX helpers (compute_103-safe: sm_80-class features only)
// ---------------------------------------------------------------------------
__device__ __forceinline__ uint32_t smem_u32(const void* p) {
    uint32_t a;
    asm("{ .reg .u64 t; cvta.to.shared.u64 t, %1; cvt.u32.u64 %0, t; }"
        : "=r"(a) : "l"(p));
    return a;
}
#define CP_ASYNC16(dst, src, sz) \
    asm volatile("cp.async.cg.shared.global [%0], [%1], 16, %2;" \
        :: "r"(dst), "l"(src), "r"(sz) : "memory")
#define CP_COMMIT() asm volatile("cp.async.commit_group;" ::: "memory")
#define CP_WAIT0()  asm volatile("cp.async.wait_group 0;" ::: "memory")
#define CP_WAIT1()  asm volatile("cp.async.wait_group 1;" ::: "memory")

#define LDSM_X4(r, addr) \
    asm volatile("ldmatrix.sync.aligned.m8n8.x4.shared.b16 {%0,%1,%2,%3}, [%4];" \
        : "=r"((r)[0]), "=r"((r)[1]), "=r"((r)[2]), "=r"((r)[3]) : "r"(addr))

#define MMA16816(d, a, b0v, b1v) \
    asm volatile("mma.sync.aligned.m16n8k16.row.col.f32.f16.f16.f32 " \
        "{%0,%1,%2,%3}, {%4,%5,%6,%7}, {%8,%9}, {%0,%1,%2,%3};" \
        : "+f"((d)[0]), "+f"((d)[1]), "+f"((d)[2]), "+f"((d)[3]) \
        : "r"((a)[0]), "r"((a)[1]), "r"((a)[2]), "r"((a)[3]), \
          "r"(b0v), "r"(b1v))

// ---------------------------------------------------------------------------
// Kernel 1 (fused): binarize+NHWC transpose (z<32) AND weight transpose (z==32)
// ---------------------------------------------------------------------------
__global__ void prep_kernel(const float* __restrict__ x,
                            const float* __restrict__ w) {
    const int tid = threadIdx.x;

    if (blockIdx.z == 32) {
        int b = blockIdx.y * 49 + blockIdx.x;        // 0..391
        #pragma unroll
        for (int k = 0; k < 6; k++) {
            int idx = b * 1536 + k * 256 + tid;
            if (idx < COUT * CIN * KTAPS) {
                int oc  = idx / (CIN * KTAPS);
                int rem = idx % (CIN * KTAPS);
                int ci  = rem / KTAPS;
                int tap = rem % KTAPS;
                g_w[((size_t)tap * COUT + oc) * CIN + ci] = __float2half(w[idx]);
            }
        }
        return;
    }

    __shared__ __half2 s[32][33];
    const int n = blockIdx.z, ci0 = blockIdx.y * 32, pos0 = blockIdx.x * 64;

    #pragma unroll
    for (int i = 0; i < 4; i++) {
        int unit = tid + i * 256;
        int cl = unit >> 5;
        int pp = unit & 31;
        float2 v = *reinterpret_cast<const float2*>(
            x + ((size_t)(n * CIN + ci0 + cl) * HW + pos0 + pp * 2));
        float m = 0.5f * (fabsf(v.x) + fabsf(v.y));
        float a = (v.x == 0.0f) ? 0.0f : copysignf(m, v.x);
        float b = (v.y == 0.0f) ? 0.0f : copysignf(m, v.y);
        s[pp][cl] = __halves2half2(__float2half(a), __float2half(b));
    }
    __syncthreads();

    const int pl = tid >> 2;
    const int c8 = tid & 3;
    const int pp = pl >> 1;
    const int hi = pl & 1;

    uint32_t wv[4];
    #pragma unroll
    for (int k = 0; k < 4; k++) {
        __half2 t0 = s[pp][c8 * 8 + 2 * k];
        __half2 t1 = s[pp][c8 * 8 + 2 * k + 1];
        __half a0 = hi ? __high2half(t0) : __low2half(t0);
        __half a1 = hi ? __high2half(t1) : __low2half(t1);
        wv[k] = (uint32_t)__half_as_ushort(a0) |
                ((uint32_t)__half_as_ushort(a1) << 16);
    }
    size_t dst = ((size_t)n * HW + pos0 + pl) * CIN + ci0 + c8 * 8;
    *reinterpret_cast<uint4*>(g_a + dst) = make_uint4(wv[0], wv[1], wv[2], wv[3]);
}

// ---------------------------------------------------------------------------
// Kernel 2: implicit-GEMM conv. CTA 96M x 128N, 4 warps (2x2), warp 48x64.
// Single A halo buffer (split preload) + 3-stage B ring (depth-2 prefetch).
// 3 CTAs/SM. acc indexed by compile-time values only. Every cp.async consume
// path is wait_group + __syncthreads() (cross-warp visibility).
// ---------------------------------------------------------------------------
__global__ __launch_bounds__(THREADS, 3)
void conv_hmma_kernel(const float* __restrict__ bias, float* __restrict__ out) {
    extern __shared__ __align__(1024) char smem[];
    __shared__ float s_bias[N_TILE];

    const int tid  = threadIdx.x;
    const int warp = tid >> 5;
    const int lane = tid & 31;
    const int m0   = blockIdx.x * M_TILE;
    const int oc0  = blockIdx.y * N_TILE;
    const uint32_t sb = smem_u32(smem);

    s_bias[tid] = bias[oc0 + tid];

    // ---- A loader over a row range [row_lo, row_hi) of one ci-chunk ----
    auto load_A_rows = [&](int cic, int row_lo, int row_hi) {
        int total = (row_hi - row_lo) * 8;
        for (int base = 0; base < total; base += THREADS) {
            int unit = base + tid;
            if (unit < total) {
                int row = row_lo + (unit >> 3), seg = unit & 7;
                int m   = m0 - 57 + row;
                bool v  = (row < ZROW) && (m >= 0) && (m < M_TOT);
                int mc  = v ? m : 0;
                const __half* src = g_a + (size_t)mc * CIN + cic * KC + seg * 8;
                uint32_t dst = sb + (uint32_t)(row * 128 +
                               ((seg ^ (row & 7)) << 4));
                CP_ASYNC16(dst, src, v ? 16 : 0);
            }
        }
    };

    // ---- B loader: 128 oc x 64 ci for one (tap, ci-chunk) ----
    auto load_B = [&](int tap, int cic, int bbuf) {
        uint32_t bb = sb + A_TILE_B + bbuf * B_BYTES;
        const __half* wsrc = g_w + (size_t)tap * COUT * CIN +
                             (size_t)oc0 * CIN + cic * KC;
        #pragma unroll
        for (int i = 0; i < 8; i++) {
            int unit = tid + i * THREADS;           // 0..1023
            int r = unit >> 3, u = unit & 7;
            CP_ASYNC16(bb + (uint32_t)(r * 128 + ((u ^ (r & 7)) << 4)),
                       wsrc + r * CIN + u * 8, 16);
        }
    };

    // ---- consumer geometry: 2x2 warp grid, warp tile 48x64 ----
    const int wm = warp >> 1, wn = warp & 1;
    int hh[3], ww[3], r0[3];
    #pragma unroll
    for (int mt = 0; mt < 3; mt++) {
        int m_local = wm * 48 + mt * 16 + (lane & 15);
        int pos = (m0 + m_local) % HW;              // safe even if m>=M_TOT
        hh[mt] = pos / HW_W;
        ww[mt] = pos - hh[mt] * HW_W;
        r0[mt] = m_local + 57;
    }
    const int ach   = lane >> 4;
    const int brow0 = wn * 64 + (lane & 7) + ((lane >> 4) << 3);  // + ng*16
    const int bch   = (lane >> 3) & 1;

    float acc[3][8][4];
    #pragma unroll
    for (int i = 0; i < 3; i++)
        #pragma unroll
        for (int j = 0; j < 8; j++)
            #pragma unroll
            for (int k = 0; k < 4; k++) acc[i][j][k] = 0.0f;

    auto compute_chunk = [&](int tap, int bbuf) {
        const int dy = tap / 3 - 1;
        const int dx = tap - (tap / 3) * 3 - 1;
        const int shift = dy * HW_W + dx;
        uint32_t Bb = sb + A_TILE_B + bbuf * B_BYTES;
        uint32_t rowbase[3]; int rx[3];
        #pragma unroll
        for (int mt = 0; mt < 3; mt++) {
            int h2 = hh[mt] + dy, w2 = ww[mt] + dx;
            bool v = ((unsigned)h2 < HW_H) && ((unsigned)w2 < HW_W);
            int row = v ? (r0[mt] + shift) : ZROW;
            rowbase[mt] = sb + (uint32_t)(row * 128);
            rx[mt] = row & 7;
        }
        #pragma unroll
        for (int ks = 0; ks < 4; ks++) {
            uint32_t b[4][4];
            #pragma unroll
            for (int ng = 0; ng < 4; ng++) {
                int row = brow0 + ng * 16;
                LDSM_X4(b[ng], Bb + (uint32_t)(row * 128 +
                        (((ks * 2 + bch) ^ (row & 7)) << 4)));
            }
            #pragma unroll
            for (int mt = 0; mt < 3; mt++) {
                uint32_t a[4];
                LDSM_X4(a, rowbase[mt] +
                        (uint32_t)(((ks * 2 + ach) ^ rx[mt]) << 4));
                #pragma unroll
                for (int ng = 0; ng < 4; ng++) {
                    MMA16816(acc[mt][2 * ng],     a, b[ng][0], b[ng][1]);
                    MMA16816(acc[mt][2 * ng + 1], a, b[ng][2], b[ng][3]);
                }
            }
        }
    };

    // ---- pipeline prologue: {A(0)+B(0)} and {B(1)} ----
    load_A_rows(0, 0, A_ROWS);
    load_B(0, 0, 0);
    CP_COMMIT();                        // group: A0 + B0  (slot 0)
    load_B(1, 0, 1);
    CP_COMMIT();                        // group: B1       (slot 1)

    // ---- main loop: ci-outer / tap-inner; one B group per iteration ----
    int tap = 0, cic = 0;
    #pragma unroll 1
    for (int q = 0; q < NCHUNKS; q++) {
        // B(q) was committed in iter q-2 (depth-2): wait is (nearly) free.
        if (q == NCHUNKS - 1) CP_WAIT0(); else CP_WAIT1();
        __syncthreads();                // B(q) visible; ring slot (q+2)%3 free

        bool newA = (tap == 0) && (q > 0);
        if (newA) {
            // part1 of A(cic): rows [112,211) incl. zero row. Own group.
            load_A_rows(cic, A_SPLIT, A_ROWS);
            CP_COMMIT();
        }
        if (q + 2 < NCHUNKS) {
            // taps 6/7/8 only read A rows >=112: rows [0,112) of next ci-chunk
            // can be preloaded now, bundled with this B group (forced complete
            // two iterations later by the uniform WAIT1).
            if (tap == 6 && cic + 1 < CIN / KC)
                load_A_rows(cic + 1, 0, A_SPLIT);
            int qn = q + 2;
            load_B(qn % KTAPS, qn / KTAPS, qn % 3);
            CP_COMMIT();
        }
        if (newA) {
            CP_WAIT1();                 // forces the A part1 group
            __syncthreads();            // cross-warp visibility of A
        }

        compute_chunk(tap, q % 3);
        if (++tap == KTAPS) { tap = 0; cic++; }
    }

    // ---- epilogue: smem transpose -> coalesced NCHW stores + bias ----
    __syncthreads();
    float* epi = reinterpret_cast<float*>(smem) + warp * (64 * 33);

    // phase 0: mt 0,1 (32 rows)
    #pragma unroll
    for (int mtl = 0; mtl < 2; mtl++) {
        #pragma unroll
        for (int nt = 0; nt < 8; nt++) {
            int nloc = nt * 8 + (lane & 3) * 2;
            int mloc = mtl * 16 + (lane >> 2);
            epi[ nloc      * 33 + mloc    ] = acc[mtl][nt][0];
            epi[(nloc + 1) * 33 + mloc    ] = acc[mtl][nt][1];
            epi[ nloc      * 33 + mloc + 8] = acc[mtl][nt][2];
            epi[(nloc + 1) * 33 + mloc + 8] = acc[mtl][nt][3];
        }
    }
    __syncwarp();
    {
        int m = m0 + wm * 48 + lane;
        if (m < M_TOT) {
            int img = m / HW, pos = m % HW;
            float* ob = out + (size_t)img * COUT * HW + pos;
            #pragma unroll 4
            for (int nloc = 0; nloc < 64; nloc++) {
                int oc = wn * 64 + nloc;
                ob[(size_t)(oc0 + oc) * HW] = epi[nloc * 33 + lane] +
                                              s_bias[oc];
            }
        }
    }
    __syncwarp();

    // phase 1: mt 2 (16 rows)
    #pragma unroll
    for (int nt = 0; nt < 8; nt++) {
        int nloc = nt * 8 + (lane & 3) * 2;
        int mloc = lane >> 2;
        epi[ nloc      * 33 + mloc    ] = acc[2][nt][0];
        epi[(nloc + 1) * 33 + mloc    ] = acc[2][nt][1];
        epi[ nloc      * 33 + mloc + 8] = acc[2][nt][2];
        epi[(nloc + 1) * 33 + mloc + 8] = acc[2][nt][3];
    }
    __syncwarp();
    if (lane < 16) {
        int m = m0 + wm * 48 + 32 + lane;
        if (m < M_TOT) {
            int img = m / HW, pos = m % HW;
            float* ob = out + (size_t)img * COUT * HW + pos;
            #pragma unroll 4
            for (int nloc = 0; nloc < 64; nloc++) {
                int oc = wn * 64 + nloc;
                ob[(size_t)(oc0 + oc) * HW] = epi[nloc * 33 + lane] +
                                              s_bias[oc];
            }
        }
    }
}

// ---------------------------------------------------------------------------
// Launch
// ---------------------------------------------------------------------------
extern "C" void kernel_launch(void* const* d_in, const int* in_sizes, int n_in,
                              void* d_out, int out_size) {
    const float* x      = (const float*)d_in[0];   // [32,256,56,56]
    const float* weight = (const float*)d_in[1];   // [256,256,3,3]
    const float* bias   = (const float*)d_in[2];   // [256]
    float* out = (float*)d_out;

    // 1) fused prologue: activations (z<32) + weights (z==32)
    {
        dim3 grid(HW / 64, CIN / 32, BATCH + 1);   // (49, 8, 33)
        prep_kernel<<<grid, 256>>>(x, weight);
    }
    // 2) HMMA implicit-GEMM conv
    {
        cudaFuncSetAttribute(conv_hmma_kernel,
                             cudaFuncAttributeMaxDynamicSharedMemorySize,
                             SMEM_DYN);
        dim3 grid(M_TILES, COUT / N_TILE);         // (1046, 2)
        conv_hmma_kernel<<<grid, THREADS, SMEM_DYN>>>(bias, out);
    }
    (void)in_sizes; (void)n_in; (void)out_size;
}

// round 15
// speedup vs baseline: 1.0748x; 1.0748x over previous
#include <cuda_runtime.h>
#include <cuda_fp16.h>
#include <math.h>
#include <stdint.h>

// ---------------------------------------------------------------------------
// Problem constants
// ---------------------------------------------------------------------------
#define BATCH 32
#define CIN   256
#define COUT  256
#define HW_H  56
#define HW_W  56
#define HW    3136
#define KTAPS 9
#define M_TOT (BATCH * HW)               // 100352

#define M_TILE   96
#define N_TILE   128
#define THREADS  128                     // 4 warps (2x2), warp tile 48x64
#define KC       64                      // ci per K chunk (4 k16 steps)
#define NCHUNKS  (KTAPS * (CIN / KC))    // 36
#define M_TILES  ((M_TOT + M_TILE - 1) / M_TILE)   // 1046 (last partial)

// A halo tile: rows m0-57 .. m0+152 (210 rows) + 1 zero row, one ci-chunk.
// Row-usage: taps 0-2 (dy=-1) read rows <=97; taps 3-5 rows 56..153;
// taps 6-8 (dy=+1) read rows >=112 (plus ZROW). So rows [0,112) of the NEXT
// ci-chunk can be preloaded at tap 6, and rows [112,210) of the current
// ci-chunk are not needed until tap 3.
#define A_ROWS   211
#define ZROW     210                     // zeroed once in prologue, never reloaded
#define A_SPLIT  112
#define A_TILE_B (A_ROWS * 128)          // 27008
#define B_BYTES  (N_TILE * KC * 2)       // 16384
#define SMEM_DYN (A_TILE_B + 2 * B_BYTES) // 59776 -> 3 CTAs/SM

// ---------------------------------------------------------------------------
// Global scratch
// ---------------------------------------------------------------------------
__device__ __align__(16) __half g_a[(size_t)M_TOT * CIN];    // NHWC fp16
__device__ __align__(16) __half g_w[KTAPS * COUT * CIN];     // [tap][oc][ci]

// ---------------------------------------------------------------------------
// PTX helpers (compute_103-safe: sm_80-class features only)
// ---------------------------------------------------------------------------
__device__ __forceinline__ uint32_t smem_u32(const void* p) {
    uint32_t a;
    asm("{ .reg .u64 t; cvta.to.shared.u64 t, %1; cvt.u32.u64 %0, t; }"
        : "=r"(a) : "l"(p));
    return a;
}
#define CP_ASYNC16(dst, src, sz) \
    asm volatile("cp.async.cg.shared.global [%0], [%1], 16, %2;" \
        :: "r"(dst), "l"(src), "r"(sz) : "memory")
#define CP_COMMIT() asm volatile("cp.async.commit_group;" ::: "memory")
#define CP_WAIT0()  asm volatile("cp.async.wait_group 0;" ::: "memory")

#define LDSM_X4(r, addr) \
    asm volatile("ldmatrix.sync.aligned.m8n8.x4.shared.b16 {%0,%1,%2,%3}, [%4];" \
        : "=r"((r)[0]), "=r"((r)[1]), "=r"((r)[2]), "=r"((r)[3]) : "r"(addr))

#define MMA16816(d, a, b0v, b1v) \
    asm volatile("mma.sync.aligned.m16n8k16.row.col.f32.f16.f16.f32 " \
        "{%0,%1,%2,%3}, {%4,%5,%6,%7}, {%8,%9}, {%0,%1,%2,%3};" \
        : "+f"((d)[0]), "+f"((d)[1]), "+f"((d)[2]), "+f"((d)[3]) \
        : "r"((a)[0]), "r"((a)[1]), "r"((a)[2]), "r"((a)[3]), \
          "r"(b0v), "r"(b1v))

// ---------------------------------------------------------------------------
// Kernel 1 (fused): binarize+NHWC transpose (z<32) AND weight transpose (z==32)
// ---------------------------------------------------------------------------
__global__ void prep_kernel(const float* __restrict__ x,
                            const float* __restrict__ w) {
    const int tid = threadIdx.x;

    if (blockIdx.z == 32) {
        int b = blockIdx.y * 49 + blockIdx.x;        // 0..391
        #pragma unroll
        for (int k = 0; k < 6; k++) {
            int idx = b * 1536 + k * 256 + tid;
            if (idx < COUT * CIN * KTAPS) {
                int oc  = idx / (CIN * KTAPS);
                int rem = idx % (CIN * KTAPS);
                int ci  = rem / KTAPS;
                int tap = rem % KTAPS;
                g_w[((size_t)tap * COUT + oc) * CIN + ci] = __float2half(w[idx]);
            }
        }
        return;
    }

    __shared__ __half2 s[32][33];
    const int n = blockIdx.z, ci0 = blockIdx.y * 32, pos0 = blockIdx.x * 64;

    #pragma unroll
    for (int i = 0; i < 4; i++) {
        int unit = tid + i * 256;
        int cl = unit >> 5;
        int pp = unit & 31;
        float2 v = *reinterpret_cast<const float2*>(
            x + ((size_t)(n * CIN + ci0 + cl) * HW + pos0 + pp * 2));
        float m = 0.5f * (fabsf(v.x) + fabsf(v.y));
        float a = (v.x == 0.0f) ? 0.0f : copysignf(m, v.x);
        float b = (v.y == 0.0f) ? 0.0f : copysignf(m, v.y);
        s[pp][cl] = __halves2half2(__float2half(a), __float2half(b));
    }
    __syncthreads();

    const int pl = tid >> 2;
    const int c8 = tid & 3;
    const int pp = pl >> 1;
    const int hi = pl & 1;

    uint32_t wv[4];
    #pragma unroll
    for (int k = 0; k < 4; k++) {
        __half2 t0 = s[pp][c8 * 8 + 2 * k];
        __half2 t1 = s[pp][c8 * 8 + 2 * k + 1];
        __half a0 = hi ? __high2half(t0) : __low2half(t0);
        __half a1 = hi ? __high2half(t1) : __low2half(t1);
        wv[k] = (uint32_t)__half_as_ushort(a0) |
                ((uint32_t)__half_as_ushort(a1) << 16);
    }
    size_t dst = ((size_t)n * HW + pos0 + pl) * CIN + ci0 + c8 * 8;
    *reinterpret_cast<uint4*>(g_a + dst) = make_uint4(wv[0], wv[1], wv[2], wv[3]);
}

// ---------------------------------------------------------------------------
// Kernel 2: implicit-GEMM conv. CTA 96M x 128N, 4 warps (2x2), warp 48x64.
// Single A halo buffer with SPLIT preload (no exposed A wait) + 2-stage B ring.
// 3 CTAs/SM. acc indexed by compile-time values only. cp.async consumption is
// always ordered by FIFO wait_group + __syncthreads at the next iter start.
// ---------------------------------------------------------------------------
__global__ __launch_bounds__(THREADS, 3)
void conv_hmma_kernel(const float* __restrict__ bias, float* __restrict__ out) {
    extern __shared__ __align__(1024) char smem[];
    __shared__ float s_bias[N_TILE];

    const int tid  = threadIdx.x;
    const int warp = tid >> 5;
    const int lane = tid & 31;
    const int m0   = blockIdx.x * M_TILE;
    const int oc0  = blockIdx.y * N_TILE;
    const uint32_t sb = smem_u32(smem);

    s_bias[tid] = bias[oc0 + tid];

    // ---- A loader over a row range [row_lo, row_hi) of one ci-chunk ----
    auto load_A_rows = [&](int cic, int row_lo, int row_hi) {
        int total = (row_hi - row_lo) * 8;
        for (int base = 0; base < total; base += THREADS) {
            int unit = base + tid;
            if (unit < total) {
                int row = row_lo + (unit >> 3), seg = unit & 7;
                int m   = m0 - 57 + row;
                bool v  = (row < ZROW) && (m >= 0) && (m < M_TOT);
                int mc  = v ? m : 0;
                const __half* src = g_a + (size_t)mc * CIN + cic * KC + seg * 8;
                uint32_t dst = sb + (uint32_t)(row * 128 +
                               ((seg ^ (row & 7)) << 4));
                CP_ASYNC16(dst, src, v ? 16 : 0);
            }
        }
    };

    // ---- B loader: 128 oc x 64 ci for one (tap, ci-chunk) ----
    auto load_B = [&](int tap, int cic, int bbuf) {
        uint32_t bb = sb + A_TILE_B + bbuf * B_BYTES;
        const __half* wsrc = g_w + (size_t)tap * COUT * CIN +
                             (size_t)oc0 * CIN + cic * KC;
        #pragma unroll
        for (int i = 0; i < 8; i++) {
            int unit = tid + i * THREADS;           // 0..1023
            int r = unit >> 3, u = unit & 7;
            CP_ASYNC16(bb + (uint32_t)(r * 128 + ((u ^ (r & 7)) << 4)),
                       wsrc + r * CIN + u * 8, 16);
        }
    };

    // ---- consumer geometry: 2x2 warp grid, warp tile 48x64 ----
    const int wm = warp >> 1, wn = warp & 1;
    int hh[3], ww[3], r0[3];
    #pragma unroll
    for (int mt = 0; mt < 3; mt++) {
        int m_local = wm * 48 + mt * 16 + (lane & 15);
        int pos = (m0 + m_local) % HW;              // safe even if m>=M_TOT
        hh[mt] = pos / HW_W;
        ww[mt] = pos - hh[mt] * HW_W;
        r0[mt] = m_local + 57;
    }
    const int ach   = lane >> 4;
    const int brow0 = wn * 64 + (lane & 7) + ((lane >> 4) << 3);  // + ng*16
    const int bch   = (lane >> 3) & 1;

    float acc[3][8][4];
    #pragma unroll
    for (int i = 0; i < 3; i++)
        #pragma unroll
        for (int j = 0; j < 8; j++)
            #pragma unroll
            for (int k = 0; k < 4; k++) acc[i][j][k] = 0.0f;

    auto compute_chunk = [&](int tap, int bbuf) {
        const int dy = tap / 3 - 1;
        const int dx = tap - (tap / 3) * 3 - 1;
        const int shift = dy * HW_W + dx;
        uint32_t Bb = sb + A_TILE_B + bbuf * B_BYTES;
        uint32_t rowbase[3]; int rx[3];
        #pragma unroll
        for (int mt = 0; mt < 3; mt++) {
            int h2 = hh[mt] + dy, w2 = ww[mt] + dx;
            bool v = ((unsigned)h2 < HW_H) && ((unsigned)w2 < HW_W);
            int row = v ? (r0[mt] + shift) : ZROW;
            rowbase[mt] = sb + (uint32_t)(row * 128);
            rx[mt] = row & 7;
        }
        #pragma unroll
        for (int ks = 0; ks < 4; ks++) {
            uint32_t b[4][4];
            #pragma unroll
            for (int ng = 0; ng < 4; ng++) {
                int row = brow0 + ng * 16;
                LDSM_X4(b[ng], Bb + (uint32_t)(row * 128 +
                        (((ks * 2 + bch) ^ (row & 7)) << 4)));
            }
            #pragma unroll
            for (int mt = 0; mt < 3; mt++) {
                uint32_t a[4];
                LDSM_X4(a, rowbase[mt] +
                        (uint32_t)(((ks * 2 + ach) ^ rx[mt]) << 4));
                #pragma unroll
                for (int ng = 0; ng < 4; ng++) {
                    MMA16816(acc[mt][2 * ng],     a, b[ng][0], b[ng][1]);
                    MMA16816(acc[mt][2 * ng + 1], a, b[ng][2], b[ng][3]);
                }
            }
        }
    };

    // ---- pipeline prologue: {A(0) full + B(0)} and {B(1)} ----
    load_A_rows(0, 0, A_ROWS);          // includes zeroing ZROW (only time)
    load_B(0, 0, 0);
    CP_COMMIT();                        // group: A0 + B0
    load_B(1, 0, 1);
    CP_COMMIT();                        // group: B1

    // ---- main loop: ci-outer / tap-inner; split-A preload, no exposed waits
    // Commit order at tap==0: part1-A BEFORE B(q+1), so tap-1's WAIT0 forces
    // part1 (needed first at tap 3). tap 0 computes with part0 (preloaded at
    // tap 6 of the previous cic) + B(q): nothing extra to wait on.
    int tap = 0, cic = 0;
    #pragma unroll 1
    for (int q = 0; q < NCHUNKS; q++) {
        CP_WAIT0();                     // forces B(q) and all earlier groups
        __syncthreads();                // cross-warp visibility; ring slot free

        if (tap == 0 && q > 0) {
            load_A_rows(cic, A_SPLIT, ZROW);      // part1: rows [112,210)
            CP_COMMIT();
        }
        if (q + 1 < NCHUNKS) {
            if (tap == 6 && cic + 1 < CIN / KC)
                load_A_rows(cic + 1, 0, A_SPLIT); // part0 of next ci-chunk
            load_B((q + 1) % KTAPS, (q + 1) / KTAPS, (q + 1) & 1);
            CP_COMMIT();
        }

        compute_chunk(tap, q & 1);
        if (++tap == KTAPS) { tap = 0; cic++; }
    }

    // ---- epilogue: smem transpose -> coalesced NCHW stores + bias ----
    __syncthreads();
    float* epi = reinterpret_cast<float*>(smem) + warp * (64 * 33);

    // phase 0: mt 0,1 (32 rows)
    #pragma unroll
    for (int mtl = 0; mtl < 2; mtl++) {
        #pragma unroll
        for (int nt = 0; nt < 8; nt++) {
            int nloc = nt * 8 + (lane & 3) * 2;
            int mloc = mtl * 16 + (lane >> 2);
            epi[ nloc      * 33 + mloc    ] = acc[mtl][nt][0];
            epi[(nloc + 1) * 33 + mloc    ] = acc[mtl][nt][1];
            epi[ nloc      * 33 + mloc + 8] = acc[mtl][nt][2];
            epi[(nloc + 1) * 33 + mloc + 8] = acc[mtl][nt][3];
        }
    }
    __syncwarp();
    {
        int m = m0 + wm * 48 + lane;
        if (m < M_TOT) {
            int img = m / HW, pos = m % HW;
            float* ob = out + (size_t)img * COUT * HW + pos;
            #pragma unroll 4
            for (int nloc = 0; nloc < 64; nloc++) {
                int oc = wn * 64 + nloc;
                ob[(size_t)(oc0 + oc) * HW] = epi[nloc * 33 + lane] +
                                              s_bias[oc];
            }
        }
    }
    __syncwarp();

    // phase 1: mt 2 (16 rows)
    #pragma unroll
    for (int nt = 0; nt < 8; nt++) {
        int nloc = nt * 8 + (lane & 3) * 2;
        int mloc = lane >> 2;
        epi[ nloc      * 33 + mloc    ] = acc[2][nt][0];
        epi[(nloc + 1) * 33 + mloc    ] = acc[2][nt][1];
        epi[ nloc      * 33 + mloc + 8] = acc[2][nt][2];
        epi[(nloc + 1) * 33 + mloc + 8] = acc[2][nt][3];
    }
    __syncwarp();
    if (lane < 16) {
        int m = m0 + wm * 48 + 32 + lane;
        if (m < M_TOT) {
            int img = m / HW, pos = m % HW;
            float* ob = out + (size_t)img * COUT * HW + pos;
            #pragma unroll 4
            for (int nloc = 0; nloc < 64; nloc++) {
                int oc = wn * 64 + nloc;
                ob[(size_t)(oc0 + oc) * HW] = epi[nloc * 33 + lane] +
                                              s_bias[oc];
            }
        }
    }
}

// ---------------------------------------------------------------------------
// Launch
// ---------------------------------------------------------------------------
extern "C" void kernel_launch(void* const* d_in, const int* in_sizes, int n_in,
                              void* d_out, int out_size) {
    const float* x      = (const float*)d_in[0];   // [32,256,56,56]
    const float* weight = (const float*)d_in[1];   // [256,256,3,3]
    const float* bias   = (const float*)d_in[2];   // [256]
    float* out = (float*)d_out;

    // 1) fused prologue: activations (z<32) + weights (z==32)
    {
        dim3 grid(HW / 64, CIN / 32, BATCH + 1);   // (49, 8, 33)
        prep_kernel<<<grid, 256>>>(x, weight);
    }
    // 2) HMMA implicit-GEMM conv
    {
        cudaFuncSetAttribute(conv_hmma_kernel,
                             cudaFuncAttributeMaxDynamicSharedMemorySize,
                             SMEM_DYN);
        dim3 grid(M_TILES, COUT / N_TILE);         // (1046, 2)
        conv_hmma_kernel<<<grid, THREADS, SMEM_DYN>>>(bias, out);
    }
    (void)in_sizes; (void)n_in; (void)out_size;
}